// round 17
// baseline (speedup 1.0000x reference)
#include <cuda_runtime.h>
#include <math.h>

// h (B=4, T=4096, d=512) fp32, raw_alpha (K=4) fp32 -> out (B, T, K, d) fp32
#define T_DIM 4096
#define D_DIM 512
#define K_DIM 4
#define B_MAX 4
#define CHUNK_L 16
#define NCHUNK (T_DIM / CHUNK_L)   // 256
#define GROUP 16
#define NGROUP (NCHUNK / GROUP)    // 16
#define DDL 16                     // dd-lanes per kC block

// Scratch (allocation-free: __device__ globals)
__device__ float g_rtab2[2][T_DIM][2];                     // r[t] paired by k-half
__device__ float g_E[B_MAX * NCHUNK * D_DIM * K_DIM];      // chunk sums -> FULL carries (8MB)

__device__ __forceinline__ float sigmoid_clip_f(float x) {
    float a = 1.0f / (1.0f + expf(-x));
    return fminf(fmaxf(a, 1e-6f), 1.0f - 1e-6f);
}

__device__ __forceinline__ float4 alpha4_of(const float* ra) {
    return make_float4(sigmoid_clip_f(ra[0]), sigmoid_clip_f(ra[1]),
                       sigmoid_clip_f(ra[2]), sigmoid_clip_f(ra[3]));
}

// ---------------------------------------------------------------------------
// K1 kB: chunk sums. Thread = (b, chunk-pair, dd4): 2 sequential chunks,
// 4 d-lanes (float4 loads) x 4 k. 65536 threads, 32 LDG.128 each -> 2.1M loads.
// ---------------------------------------------------------------------------
__global__ __launch_bounds__(256) void kB_chunks(const float* __restrict__ h,
                                                 const float* __restrict__ raw_alpha,
                                                 int Bn) {
    const int DV  = D_DIM / 4;        // 128 d-quads
    const int NCP = NCHUNK / 2;       // 128 chunk-pairs
    int tid = blockIdx.x * blockDim.x + threadIdx.x;
    int ddv = tid % DV;
    int cp  = (tid / DV) % NCP;
    int b   = tid / (DV * NCP);
    if (b >= Bn) return;
    int dd = ddv * 4;

    const float4 a4 = alpha4_of(raw_alpha);
    const float4* hp = (const float4*)(h + ((size_t)b * T_DIM + (size_t)cp * 2 * CHUNK_L) * D_DIM + dd);

#pragma unroll
    for (int cc = 0; cc < 2; cc++) {
        float4 S0 = make_float4(0.f, 0.f, 0.f, 0.f);
        float4 S1 = S0, S2 = S0, S3 = S0;
#pragma unroll
        for (int j = 0; j < CHUNK_L; j++) {
            float4 h4 = hp[(size_t)(cc * CHUNK_L + j) * DV];
            S0.x = fmaf(a4.x, S0.x, h4.x); S0.y = fmaf(a4.y, S0.y, h4.x);
            S0.z = fmaf(a4.z, S0.z, h4.x); S0.w = fmaf(a4.w, S0.w, h4.x);
            S1.x = fmaf(a4.x, S1.x, h4.y); S1.y = fmaf(a4.y, S1.y, h4.y);
            S1.z = fmaf(a4.z, S1.z, h4.y); S1.w = fmaf(a4.w, S1.w, h4.y);
            S2.x = fmaf(a4.x, S2.x, h4.z); S2.y = fmaf(a4.y, S2.y, h4.z);
            S2.z = fmaf(a4.z, S2.z, h4.z); S2.w = fmaf(a4.w, S2.w, h4.z);
            S3.x = fmaf(a4.x, S3.x, h4.w); S3.y = fmaf(a4.y, S3.y, h4.w);
            S3.z = fmaf(a4.z, S3.z, h4.w); S3.w = fmaf(a4.w, S3.w, h4.w);
        }
        int c = cp * 2 + cc;
        float4* Ep = (float4*)&g_E[(((size_t)b * NCHUNK + c) * D_DIM + dd) * K_DIM];
        Ep[0] = S0; Ep[1] = S1; Ep[2] = S2; Ep[3] = S3;
    }
}

// ---------------------------------------------------------------------------
// K2 kC: convert chunk sums into FULL carries, in place.
// Block = (b, 16-dd-lane tile). Thread = (g, ddl). Also: fp32 r-table side job.
// ---------------------------------------------------------------------------
__global__ __launch_bounds__(256) void kC_carry(const float* __restrict__ raw_alpha, int Bn) {
    __shared__ float4 gs[GROUP][DDL];

    // side job: r-table (fp32, cancellation-safe), paired layout.
    int gtid = blockIdx.x * blockDim.x + threadIdx.x;
    if (gtid < T_DIM) {
        int t = gtid;
        float r[K_DIM];
#pragma unroll
        for (int k = 0; k < K_DIM; k++) {
            float oma = 1.0f / (1.0f + expf(raw_alpha[k]));        // 1 - sigmoid(x)
            oma = fminf(fmaxf(oma, 1e-6f), 1.0f - 1e-6f);
            float la  = log1pf(-oma);                              // log(alpha)
            float den = -expm1f((float)(t + 1) * la);              // 1 - alpha^{t+1}
            r[k] = oma / den;
        }
        g_rtab2[0][t][0] = r[0]; g_rtab2[0][t][1] = r[1];
        g_rtab2[1][t][0] = r[2]; g_rtab2[1][t][1] = r[3];
    }

    int tid = threadIdx.x;
    int ddl = tid % DDL;                 // 0..15
    int g   = tid / DDL;                 // 0..15
    int ddt = blockIdx.x % (D_DIM / DDL);
    int b   = blockIdx.x / (D_DIM / DDL);
    if (b >= Bn) return;
    int dd  = ddt * DDL + ddl;

    float4 q = alpha4_of(raw_alpha);
#pragma unroll
    for (int s = 0; s < 4; s++) { q.x *= q.x; q.y *= q.y; q.z *= q.z; q.w *= q.w; } // alpha^16
    float4 Q = q;
#pragma unroll
    for (int s = 0; s < 4; s++) { Q.x *= Q.x; Q.y *= Q.y; Q.z *= Q.z; Q.w *= Q.w; } // alpha^256

    float4* Ep = (float4*)&g_E[(((size_t)b * NCHUNK + (size_t)g * GROUP) * D_DIM + dd) * K_DIM];
    float4 snap[GROUP];
    float4 P = make_float4(0.f, 0.f, 0.f, 0.f);
#pragma unroll
    for (int i = 0; i < GROUP; i++) {
        float4 e = Ep[(size_t)i * D_DIM];
        P.x = fmaf(q.x, P.x, e.x);
        P.y = fmaf(q.y, P.y, e.y);
        P.z = fmaf(q.z, P.z, e.z);
        P.w = fmaf(q.w, P.w, e.w);
        snap[i] = P;
    }
    gs[g][ddl] = P;   // group sum
    __syncthreads();

    if (g == 0) {
        float4 carry = make_float4(0.f, 0.f, 0.f, 0.f);
#pragma unroll
        for (int gg = 0; gg < GROUP; gg++) {
            float4 s = gs[gg][ddl];
            gs[gg][ddl] = carry;
            carry.x = fmaf(Q.x, carry.x, s.x);
            carry.y = fmaf(Q.y, carry.y, s.y);
            carry.z = fmaf(Q.z, carry.z, s.z);
            carry.w = fmaf(Q.w, carry.w, s.w);
        }
    }
    __syncthreads();

    float4 gc = gs[g][ddl];
    float4 prevP = make_float4(0.f, 0.f, 0.f, 0.f);
#pragma unroll
    for (int i = 0; i < GROUP; i++) {
        Ep[(size_t)i * D_DIM] = make_float4(gc.x + prevP.x, gc.y + prevP.y,
                                            gc.z + prevP.z, gc.w + prevP.w);
        gc.x *= q.x; gc.y *= q.y; gc.z *= q.z; gc.w *= q.w;
        prevP = snap[i];
    }
}

// ---------------------------------------------------------------------------
// K3 kD: final scan + normalize + store. Thread = (b, c, kh, dd4).
// r loads are now one float2 per step (paired table layout).
// ---------------------------------------------------------------------------
__global__ __launch_bounds__(256) void kD_final(const float* __restrict__ h,
                                                const float* __restrict__ raw_alpha,
                                                float* __restrict__ out, int Bn) {
    int c   = blockIdx.x % NCHUNK;
    int b   = blockIdx.x / NCHUNK;
    if (b >= Bn) return;
    int tid = threadIdx.x;
    int ddv = tid & 127;          // 0..127
    int kh  = tid >> 7;           // 0..1
    int dd  = ddv * 4;

    float2 a2 = make_float2(sigmoid_clip_f(raw_alpha[kh * 2]),
                            sigmoid_clip_f(raw_alpha[kh * 2 + 1]));

    const float* Lb = &g_E[(((size_t)b * NCHUNK + c) * D_DIM + dd) * K_DIM + kh * 2];
    float2 S0 = *(const float2*)(Lb + 0);
    float2 S1 = *(const float2*)(Lb + 4);
    float2 S2 = *(const float2*)(Lb + 8);
    float2 S3 = *(const float2*)(Lb + 12);

    const float* hp = h + ((size_t)b * T_DIM + (size_t)c * CHUNK_L) * D_DIM + dd;
    float*       op = out + (((size_t)b * T_DIM + (size_t)c * CHUNK_L) * K_DIM + kh * 2) * D_DIM + dd;
    const float2* rp = (const float2*)&g_rtab2[kh][c * CHUNK_L][0];

#pragma unroll
    for (int j = 0; j < CHUNK_L; j++) {
        float4 h4 = *(const float4*)(hp + (size_t)j * D_DIM);
        float2 r2 = __ldg(rp + j);

        S0.x = fmaf(a2.x, S0.x, h4.x); S0.y = fmaf(a2.y, S0.y, h4.x);
        S1.x = fmaf(a2.x, S1.x, h4.y); S1.y = fmaf(a2.y, S1.y, h4.y);
        S2.x = fmaf(a2.x, S2.x, h4.z); S2.y = fmaf(a2.y, S2.y, h4.z);
        S3.x = fmaf(a2.x, S3.x, h4.w); S3.y = fmaf(a2.y, S3.y, h4.w);

        float4 olo = make_float4(S0.x * r2.x, S1.x * r2.x, S2.x * r2.x, S3.x * r2.x);
        float4 ohi = make_float4(S0.y * r2.y, S1.y * r2.y, S2.y * r2.y, S3.y * r2.y);

        float* ob = op + (size_t)j * K_DIM * D_DIM;
        __stcs((float4*)(ob + 0 * D_DIM), olo);
        __stcs((float4*)(ob + 1 * D_DIM), ohi);
    }
}

// ---------------------------------------------------------------------------
extern "C" void kernel_launch(void* const* d_in, const int* in_sizes, int n_in,
                              void* d_out, int out_size) {
    const float* h         = (const float*)d_in[0];
    const float* raw_alpha = (const float*)d_in[1];
    int h_elems = in_sizes[0];
    if (n_in >= 2 && in_sizes[1] > in_sizes[0]) {
        h         = (const float*)d_in[1];
        raw_alpha = (const float*)d_in[0];
        h_elems   = in_sizes[1];
    }
    float* out = (float*)d_out;

    int Bn = h_elems / (T_DIM * D_DIM);
    if (Bn > B_MAX) Bn = B_MAX;
    if (Bn < 1)     Bn = 1;

    { int total = Bn * (NCHUNK / 2) * (D_DIM / 4);
      kB_chunks<<<(total + 255) / 256, 256>>>(h, raw_alpha, Bn); }

    kC_carry<<<Bn * (D_DIM / DDL), 256>>>(raw_alpha, Bn);

    kD_final<<<Bn * NCHUNK, 256>>>(h, raw_alpha, out, Bn);
}